// round 1
// baseline (speedup 1.0000x reference)
#include <cuda_runtime.h>
#include <math.h>

// Problem constants: B=32 sequences, L=256 positions, NUM_AA=20.
// w_pair[(i*L+p)*400 + j*20 + e] is a 20x20 tile per (i,p).
#define B_ 32
#define L_ 256
#define A_ 20

// Scratch (all fully overwritten every launch; no zeroing needed).
__device__ __align__(16) float g_logits[2][B_][L_][A_];   // per-half p>i logits contributions
__device__ __align__(16) float g_const[2][L_ * A_];       // per-half (p<i col19 + diag) contributions
__device__ double g_pairA[512];                            // per-CTA pair-energy partial
__device__ double g_regA[512];                             // per-CTA sum(|w|+w^2) partial over w_pair
__device__ double g_partB[32];                             // per-CTA (lse - single) partials

// ---------------------------------------------------------------------------
// Kernel A: single streaming pass over w_pair (104.9 MB). grid (L, 2), 320 thr.
// CTA (i, half) owns tiles p in [half*128, half*128+128).
// Super-tile = 16 tiles (25.6 KB) loaded as float4 (5/thread), transposed into
// smem with row stride 21 (conflict-free gathers), prefetch-pipelined.
// ---------------------------------------------------------------------------
__global__ __launch_bounds__(320) void mrf_kernelA(const int* __restrict__ x,
                                                   const float* __restrict__ wp) {
    const int i    = blockIdx.x;
    const int half = blockIdx.y;
    const int p0   = half * 128;
    const int tid  = threadIdx.x;

    __shared__ float buf[16 * 420];   // 16 tiles, each 20 rows x stride 21
    __shared__ int   xch[B_ * 128];   // x[b, p0..p0+127]
    __shared__ int   xi[B_];          // x[b, i]
    __shared__ float sredp[10];
    __shared__ float sredr[10];

    for (int n = tid; n < B_ * 128; n += 320) {
        int b = n >> 7, pl = n & 127;
        xch[n] = x[b * L_ + p0 + pl];
    }
    if (tid < B_) xi[tid] = x[tid * L_ + i];

    const float4* wp4 = reinterpret_cast<const float4*>(wp);
    const size_t base4 = ((size_t)i * L_ + p0) * 100;  // float4 units (400 floats/tile)

    // Each thread owns two (b, j) logits accumulators: idx = tid and tid+320.
    const int idx0 = tid, idx1 = tid + 320;
    const int b0 = idx0 / 20, j0 = idx0 % 20;
    const int b1 = idx1 / 20, j1 = idx1 % 20;

    float acc0 = 0.f, acc1 = 0.f, pair_acc = 0.f, reg_acc = 0.f, const_acc = 0.f;

    float4 v[5];
#pragma unroll
    for (int w = 0; w < 5; w++) v[w] = wp4[base4 + tid + w * 320];

    for (int s = 0; s < 8; s++) {
        // Store current super-tile to smem (transposed-padded) + reg sums in flight.
#pragma unroll
        for (int w = 0; w < 5; w++) {
            float4 q = v[w];
            reg_acc += fabsf(q.x) + q.x * q.x;
            reg_acc += fabsf(q.y) + q.y * q.y;
            reg_acc += fabsf(q.z) + q.z * q.z;
            reg_acc += fabsf(q.w) + q.w * q.w;
            int slot = tid + w * 320;
            int k = slot * 4;          // element index within super-tile (0..6399)
            int t = k / 400;           // tile within super-tile
            int r = k - t * 400;
            int j = r / 20;            // a float4 never crosses a j-row (20 % 4 == 0)
            int e = r - j * 20;
            float* d = &buf[t * 420 + j * 21 + e];
            d[0] = q.x; d[1] = q.y; d[2] = q.z; d[3] = q.w;
        }
        __syncthreads();

        // Prefetch next super-tile (overlaps with smem processing below).
        if (s < 7) {
            size_t nb = base4 + (size_t)(s + 1) * 1600;
#pragma unroll
            for (int w = 0; w < 5; w++) v[w] = wp4[nb + tid + w * 320];
        }

        // Process 16 tiles from smem.
#pragma unroll 4
        for (int t = 0; t < 16; t++) {
            const int p  = p0 + s * 16 + t;
            const int pl = p - p0;
            const float* bt = &buf[t * 420];
            if (p > i) {  // uniform branch across CTA
                acc0 += bt[j0 * 21 + xch[b0 * 128 + pl]];
                acc1 += bt[j1 * 21 + xch[b1 * 128 + pl]];
            }
            if (tid < 32) pair_acc += bt[xi[tid] * 21 + xch[tid * 128 + pl]];
            if (p < i && tid < 20) const_acc += bt[tid * 21 + 19];   // eff = NUM_AA-1
            if (p == i && tid < 20) const_acc += bt[tid * 22];        // diag M[j][j]
        }
        __syncthreads();
    }

    // Disjoint writes — no atomics, fully deterministic.
    g_logits[half][b0][i][j0] = acc0;
    g_logits[half][b1][i][j1] = acc1;
    if (tid < 20) g_const[half][i * 20 + tid] = const_acc;

    float pv = pair_acc, rv = reg_acc;
#pragma unroll
    for (int o = 16; o > 0; o >>= 1) {
        pv += __shfl_down_sync(0xffffffffu, pv, o);
        rv += __shfl_down_sync(0xffffffffu, rv, o);
    }
    const int wid = tid >> 5, lane = tid & 31;
    if (lane == 0) { sredp[wid] = pv; sredr[wid] = rv; }
    __syncthreads();
    if (tid == 0) {
        double ps = 0.0, rs = 0.0;
        for (int w = 0; w < 10; w++) { ps += (double)sredp[w]; rs += (double)sredr[w]; }
        const int cid = half * L_ + i;  // 0..511
        g_pairA[cid] = ps;
        g_regA[cid]  = rs;
    }
}

// ---------------------------------------------------------------------------
// Kernel B: per-row logsumexp over j=0..19 for all (b, i); subtract singles.
// ---------------------------------------------------------------------------
__global__ __launch_bounds__(256) void mrf_kernelB(const int* __restrict__ x,
                                                   const float* __restrict__ ws) {
    const int row = blockIdx.x * 256 + threadIdx.x;  // 0..8191
    const int b = row >> 8;
    const int i = row & 255;

    const float4* a0 = reinterpret_cast<const float4*>(&g_logits[0][b][i][0]);
    const float4* a1 = reinterpret_cast<const float4*>(&g_logits[1][b][i][0]);
    const float4* c0 = reinterpret_cast<const float4*>(&g_const[0][i * 20]);
    const float4* c1 = reinterpret_cast<const float4*>(&g_const[1][i * 20]);
    const float4* s4 = reinterpret_cast<const float4*>(ws + i * 20);

    float vals[20];
    float m = -3.0e38f;
#pragma unroll
    for (int q = 0; q < 5; q++) {
        float4 A = a0[q], Bv = a1[q], C = c0[q], D = c1[q], S = s4[q];
        vals[q * 4 + 0] = A.x + Bv.x + C.x + D.x + S.x;
        vals[q * 4 + 1] = A.y + Bv.y + C.y + D.y + S.y;
        vals[q * 4 + 2] = A.z + Bv.z + C.z + D.z + S.z;
        vals[q * 4 + 3] = A.w + Bv.w + C.w + D.w + S.w;
        m = fmaxf(m, fmaxf(fmaxf(vals[q * 4 + 0], vals[q * 4 + 1]),
                           fmaxf(vals[q * 4 + 2], vals[q * 4 + 3])));
    }
    float se = 0.f;
#pragma unroll
    for (int j = 0; j < 20; j++) se += expf(vals[j] - m);
    const float lse  = m + logf(se);
    const float sing = ws[i * 20 + x[row]];   // x[b*L + i] == x[row]
    double val = (double)lse - (double)sing;

    __shared__ double sred[8];
#pragma unroll
    for (int o = 16; o > 0; o >>= 1) val += __shfl_down_sync(0xffffffffu, val, o);
    if ((threadIdx.x & 31) == 0) sred[threadIdx.x >> 5] = val;
    __syncthreads();
    if (threadIdx.x == 0) {
        double s = 0.0;
        for (int w = 0; w < 8; w++) s += sred[w];
        g_partB[blockIdx.x] = s;
    }
}

// ---------------------------------------------------------------------------
// Kernel C: deterministic final reduction (fixed order) + w_single reg + output.
// ---------------------------------------------------------------------------
__global__ __launch_bounds__(256) void mrf_kernelC(const float* __restrict__ ws,
                                                   float* __restrict__ out) {
    const int tid = threadIdx.x;
    double regs = 0.0, pair = 0.0, regp = 0.0, lsev = 0.0;

    for (int n = tid; n < L_ * A_; n += 256) {
        float w = ws[n];
        regs += (double)fabsf(w) + (double)w * (double)w;
    }
    for (int n = tid; n < 512; n += 256) { pair += g_pairA[n]; regp += g_regA[n]; }
    if (tid < 32) lsev = g_partB[tid];

    __shared__ double s1[8], s2[8], s3[8], s4v[8];
#pragma unroll
    for (int o = 16; o > 0; o >>= 1) {
        regs += __shfl_down_sync(0xffffffffu, regs, o);
        pair += __shfl_down_sync(0xffffffffu, pair, o);
        regp += __shfl_down_sync(0xffffffffu, regp, o);
        lsev += __shfl_down_sync(0xffffffffu, lsev, o);
    }
    const int wid = tid >> 5, lane = tid & 31;
    if (lane == 0) { s1[wid] = regs; s2[wid] = pair; s3[wid] = regp; s4v[wid] = lsev; }
    __syncthreads();
    if (tid == 0) {
        double RS = 0, PA = 0, RP = 0, LS = 0;
        for (int w = 0; w < 8; w++) { RS += s1[w]; PA += s2[w]; RP += s3[w]; LS += s4v[w]; }
        // final = mean_b sum_i (lse - single - pair_part)  + reg terms
        // LAMBDA_SINGLE = 1.0, LAMBDA_PAIR = 0.2*(L-1) = 51.0
        double res = (LS - PA) / (double)B_ + 1.0 * RS + 51.0 * RP;
        out[0] = (float)res;
    }
}

extern "C" void kernel_launch(void* const* d_in, const int* in_sizes, int n_in,
                              void* d_out, int out_size) {
    (void)in_sizes; (void)n_in; (void)out_size;
    const int*   x  = (const int*)d_in[0];
    const float* ws = (const float*)d_in[1];
    const float* wp = (const float*)d_in[2];
    float* out = (float*)d_out;

    dim3 gA(L_, 2);
    mrf_kernelA<<<gA, 320>>>(x, wp);
    mrf_kernelB<<<B_, 256>>>(x, ws);
    mrf_kernelC<<<1, 256>>>(ws, out);
}

// round 2
// speedup vs baseline: 1.0639x; 1.0639x over previous
#include <cuda_runtime.h>
#include <math.h>

#define B_ 32
#define L_ 256
#define A_ 20

// Scratch (fully overwritten every launch).
__device__ __align__(16) float g_logits[2][B_][L_][A_];   // p>i logits contributions per half
__device__ __align__(16) float g_const[2][L_ * A_];       // (p<i col19 + diag) per half
__device__ double g_pairA[512];
__device__ double g_regA[512];
__device__ double g_partB[64];
__device__ unsigned int g_bcount = 0;                      // reset by last block each launch

// ---------------------------------------------------------------------------
// Kernel A: one streaming pass over w_pair (104.9 MB). grid (L, 2), 640 thr.
// CTA (i, half) owns 128 tiles, processed in 4 super-tiles of 32 (51.2 KB),
// register-prefetched (5 float4/thread). Tiles stored row-major stride 21.
// Each thread owns ONE (b, j) logits accumulator -> ~5 instr/tile inner loop.
// ---------------------------------------------------------------------------
__global__ __launch_bounds__(640, 2) void mrf_kernelA(const int* __restrict__ x,
                                                      const float* __restrict__ wp) {
    const int i    = blockIdx.x;
    const int half = blockIdx.y;
    const int p0   = half * 128;
    const int tid  = threadIdx.x;

    __shared__ float buf[32 * 420];           // 32 tiles, 20 rows x stride 21
    __shared__ unsigned char xch8[B_ * 128];  // x[b, p0..p0+127] as bytes
    __shared__ int   xi[B_];
    __shared__ float sredr[20];

    for (int n = tid; n < B_ * 128; n += 640) {
        int b = n >> 7, pl = n & 127;
        xch8[n] = (unsigned char)x[b * L_ + p0 + pl];
    }
    if (tid < B_) xi[tid] = x[tid * L_ + i];

    const float4* wp4 = reinterpret_cast<const float4*>(wp);
    const size_t base4 = ((size_t)i * L_ + p0) * 100;   // float4 units

    const int b  = tid / 20;
    const int j  = tid % 20;
    const int jrow = j * 21;
    const unsigned char* xb = &xch8[b * 128];

    // Stage-invariant smem store offsets (floats), one per w-chunk.
    int dsto[5];
#pragma unroll
    for (int w = 0; w < 5; w++) {
        int slot = tid + w * 640;       // float4 slot 0..3199
        int t  = slot / 100;
        int r4 = slot - t * 100;        // float4 within tile
        int jj = r4 / 5;
        int ee = (r4 - jj * 5) * 4;
        dsto[w] = t * 420 + jj * 21 + ee;
    }

    float acc = 0.f, pair_acc = 0.f, const_acc = 0.f, reg_acc = 0.f;

    float4 v[5];
#pragma unroll
    for (int w = 0; w < 5; w++) v[w] = wp4[base4 + tid + w * 640];

    for (int s = 0; s < 4; s++) {
#pragma unroll
        for (int w = 0; w < 5; w++) {
            float4 q = v[w];
            reg_acc += fmaf(q.x, q.x, fabsf(q.x));
            reg_acc += fmaf(q.y, q.y, fabsf(q.y));
            reg_acc += fmaf(q.z, q.z, fabsf(q.z));
            reg_acc += fmaf(q.w, q.w, fabsf(q.w));
            float* d = &buf[dsto[w]];
            d[0] = q.x; d[1] = q.y; d[2] = q.z; d[3] = q.w;
        }
        __syncthreads();

        if (s < 3) {
            size_t nb = base4 + (size_t)(s + 1) * 3200;
#pragma unroll
            for (int w = 0; w < 5; w++) v[w] = wp4[nb + tid + w * 640];
        }

        const int pbase = p0 + s * 32;
        const int tmin  = i + 1 - pbase;          // t >= tmin  <=>  p > i
        const unsigned char* xbs = xb + s * 32;

        // Main gather loop: all 640 threads, ~5 instr/tile.
#pragma unroll 8
        for (int t = 0; t < 32; t++) {
            int e = xbs[t];
            if (t >= tmin) acc += buf[t * 420 + jrow + e];
        }

        // Pair energy: warp 0 only (b2 = lane).
        if (tid < 32) {
            const unsigned char* xp = &xch8[tid * 128 + s * 32];
            const int ei21 = xi[tid] * 21;
#pragma unroll 8
            for (int t = 0; t < 32; t++)
                pair_acc += buf[t * 420 + ei21 + xp[t]];
        }

        // Const terms (p<i: col 19; p==i: diag): warp 2, lanes 0..19.
        if (tid >= 64 && tid < 84 && pbase <= i) {
            const int je = tid - 64;
#pragma unroll 8
            for (int t = 0; t < 32; t++) {
                int p = pbase + t;
                if (p < i)  const_acc += buf[t * 420 + je * 21 + 19];
                if (p == i) const_acc += buf[t * 420 + je * 22];
            }
        }
        __syncthreads();
    }

    // Disjoint deterministic writes.
    g_logits[half][b][i][j] = acc;
    if (tid >= 64 && tid < 84) g_const[half][i * 20 + (tid - 64)] = const_acc;

    // reg_acc: all-warp reduction; pair_acc: warp 0 reduction.
    float rv = reg_acc;
#pragma unroll
    for (int o = 16; o > 0; o >>= 1) rv += __shfl_down_sync(0xffffffffu, rv, o);
    const int wid = tid >> 5, lane = tid & 31;
    if (lane == 0) sredr[wid] = rv;

    if (tid < 32) {
        float pv = pair_acc;
#pragma unroll
        for (int o = 16; o > 0; o >>= 1) pv += __shfl_down_sync(0xffffffffu, pv, o);
        if (tid == 0) g_pairA[half * L_ + i] = (double)pv;
    }
    __syncthreads();
    if (tid == 0) {
        double rs = 0.0;
        for (int w = 0; w < 20; w++) rs += (double)sredr[w];
        g_regA[half * L_ + i] = rs;
    }
}

// ---------------------------------------------------------------------------
// Kernel B (fused with final reduce): per-row logsumexp, CTA partials,
// deterministic last-block final reduction + w_single reg + output.
// grid 64 x 128 threads; one row per thread.
// ---------------------------------------------------------------------------
__global__ __launch_bounds__(128) void mrf_kernelB(const int* __restrict__ x,
                                                   const float* __restrict__ ws,
                                                   float* __restrict__ out) {
    const int tid = threadIdx.x;
    const int row = blockIdx.x * 128 + tid;   // 0..8191
    const int bb = row >> 8;
    const int ii = row & 255;

    const float4* a0 = reinterpret_cast<const float4*>(&g_logits[0][bb][ii][0]);
    const float4* a1 = reinterpret_cast<const float4*>(&g_logits[1][bb][ii][0]);
    const float4* c0 = reinterpret_cast<const float4*>(&g_const[0][ii * 20]);
    const float4* c1 = reinterpret_cast<const float4*>(&g_const[1][ii * 20]);
    const float4* s4 = reinterpret_cast<const float4*>(ws + ii * 20);

    float vals[20];
    float m = -3.0e38f;
#pragma unroll
    for (int q = 0; q < 5; q++) {
        float4 A = a0[q], Bv = a1[q], C = c0[q], D = c1[q], S = s4[q];
        vals[q * 4 + 0] = A.x + Bv.x + C.x + D.x + S.x;
        vals[q * 4 + 1] = A.y + Bv.y + C.y + D.y + S.y;
        vals[q * 4 + 2] = A.z + Bv.z + C.z + D.z + S.z;
        vals[q * 4 + 3] = A.w + Bv.w + C.w + D.w + S.w;
        m = fmaxf(m, fmaxf(fmaxf(vals[q * 4 + 0], vals[q * 4 + 1]),
                           fmaxf(vals[q * 4 + 2], vals[q * 4 + 3])));
    }
    float se = 0.f;
#pragma unroll
    for (int jj = 0; jj < 20; jj++) se += expf(vals[jj] - m);
    const float lse  = m + logf(se);
    const float sing = ws[ii * 20 + x[row]];
    double val = (double)lse - (double)sing;

    __shared__ double sred[4];
#pragma unroll
    for (int o = 16; o > 0; o >>= 1) val += __shfl_down_sync(0xffffffffu, val, o);
    if ((tid & 31) == 0) sred[tid >> 5] = val;
    __syncthreads();
    if (tid == 0) {
        double s = 0.0;
        for (int w = 0; w < 4; w++) s += sred[w];
        g_partB[blockIdx.x] = s;
        __threadfence();
    }

    __shared__ int amLast;
    if (tid == 0) amLast = (atomicAdd(&g_bcount, 1u) == gridDim.x - 1u) ? 1 : 0;
    __syncthreads();
    if (!amLast) return;

    // Last block: fixed-order deterministic final reduction.
    double lsev = 0.0, pair = 0.0, regp = 0.0, regs = 0.0;
    if (tid < 64) lsev = g_partB[tid];
    for (int n = tid; n < 512; n += 128) { pair += g_pairA[n]; regp += g_regA[n]; }
    for (int n = tid; n < L_ * A_; n += 128) {
        float w = ws[n];
        regs += (double)fabsf(w) + (double)w * (double)w;
    }

    __shared__ double s1[4], s2[4], s3[4], s4v[4];
#pragma unroll
    for (int o = 16; o > 0; o >>= 1) {
        lsev += __shfl_down_sync(0xffffffffu, lsev, o);
        pair += __shfl_down_sync(0xffffffffu, pair, o);
        regp += __shfl_down_sync(0xffffffffu, regp, o);
        regs += __shfl_down_sync(0xffffffffu, regs, o);
    }
    if ((tid & 31) == 0) {
        int w = tid >> 5;
        s1[w] = lsev; s2[w] = pair; s3[w] = regp; s4v[w] = regs;
    }
    __syncthreads();
    if (tid == 0) {
        double LS = 0, PA = 0, RP = 0, RS = 0;
        for (int w = 0; w < 4; w++) { LS += s1[w]; PA += s2[w]; RP += s3[w]; RS += s4v[w]; }
        // LAMBDA_SINGLE = 1.0, LAMBDA_PAIR = 0.2*(L-1) = 51.0
        out[0] = (float)((LS - PA) / (double)B_ + 1.0 * RS + 51.0 * RP);
        g_bcount = 0;   // self-reset for graph replay
    }
}

extern "C" void kernel_launch(void* const* d_in, const int* in_sizes, int n_in,
                              void* d_out, int out_size) {
    (void)in_sizes; (void)n_in; (void)out_size;
    const int*   x  = (const int*)d_in[0];
    const float* ws = (const float*)d_in[1];
    const float* wp = (const float*)d_in[2];
    float* out = (float*)d_out;

    dim3 gA(L_, 2);
    mrf_kernelA<<<gA, 640>>>(x, wp);
    mrf_kernelB<<<64, 128>>>(x, ws, out);
}

// round 3
// speedup vs baseline: 1.4019x; 1.3176x over previous
#include <cuda_runtime.h>
#include <math.h>

#define B_ 32
#define L_ 256
#define A_ 20
#define TILE_F 640          // floats per transposed tile: 20 e-rows x 32 (swizzled)
#define NTHR 640

// Per-i results: {lse_sum, pair_sum, reg_sum}
__device__ double g_res[L_][3];

// Dynamic smem layout (bytes):
//   [0      , 81920)  buf: 32 tiles x 640 floats (transposed + swizzled)
//   [81920  , 90112)  xch8: x as bytes [32][256]
//   [90112  , 90240)  xi[32] (int)
//   [90240  , 90320)  wsrow[20]
//   [90320  , 90400)  csts[20]
//   [90400  , 90480)  sredr[20]
#define SMEM_BYTES 90480

__global__ __launch_bounds__(NTHR, 1) void mrf_kernelA(const int* __restrict__ x,
                                                       const float* __restrict__ ws,
                                                       const float* __restrict__ wp) {
    extern __shared__ char smem_raw[];
    float*         buf   = reinterpret_cast<float*>(smem_raw);
    unsigned char* xch8  = reinterpret_cast<unsigned char*>(smem_raw + 81920);
    int*           xi    = reinterpret_cast<int*>(smem_raw + 90112);
    float*         wsrow = reinterpret_cast<float*>(smem_raw + 90240);
    float*         csts  = reinterpret_cast<float*>(smem_raw + 90320);
    float*         sredr = reinterpret_cast<float*>(smem_raw + 90400);

    const int i    = blockIdx.x;
    const int tid  = threadIdx.x;
    const int wid  = tid >> 5;
    const int lane = tid & 31;

    // thread -> (tsub, b, jg):  tid = tsub*160 + b*5 + jg
    const int tsub = tid / 160;
    const int rr   = tid - tsub * 160;
    const int b    = rr / 5;
    const int jg   = rr - b * 5;
    const int tb   = tsub * 8 * TILE_F;

    // Issue stage-0 prefetch first (hide behind prologue).
    const float4* wp4 = reinterpret_cast<const float4*>(wp);
    const size_t base4 = (size_t)i * 25600;   // 256 tiles * 100 float4
    float4 v[5];
#pragma unroll
    for (int w = 0; w < 5; w++) v[w] = wp4[base4 + tid + w * NTHR];

    // Prologue fills.
    for (int n = tid; n < B_ * L_; n += NTHR) xch8[n] = (unsigned char)x[n];
    if (tid < B_) xi[tid] = x[tid * L_ + i];
    if (tid >= 32 && tid < 52) wsrow[tid - 32] = ws[i * A_ + (tid - 32)];

    // Stage-invariant swizzled store offsets (float4 -> 4 strided STS.32).
    int dstb[5];
#pragma unroll
    for (int w = 0; w < 5; w++) {
        int slot = tid + w * NTHR;      // 0..3199 (float4 within super-stage)
        int t  = slot / 100;
        int f  = (slot - t * 100) * 4;  // element within tile (row-major j*20+e)
        int j  = f / 20;
        int e0 = f - j * 20;            // multiple of 4
        dstb[w] = t * TILE_F + (e0 << 5) + ((((j >> 2) ^ (e0 >> 2)) & 7) << 2) + (j & 3);
    }

    float a0 = 0.f, a1 = 0.f, a2 = 0.f, a3 = 0.f;
    float reg_acc = 0.f, pair_acc = 0.f, c_acc = 0.f;

    // Pair-warp constants (warp 18) — read xi after barrier below.
    __syncthreads();
    int xihi = 0, xilo = 0;
    if (wid == 18) { int e = xi[lane]; xihi = e >> 2; xilo = e & 3; }
    const int jc   = tid - 608;  // const-warp j (valid when 0..19)
    const int co19 = 608 + ((((jc >> 2) ^ 4) & 7) << 2) + (jc & 3);

    for (int s = 0; s < 8; s++) {
        // Store super-tile transposed+swizzled; fold reg terms in flight.
#pragma unroll
        for (int w = 0; w < 5; w++) {
            float4 q = v[w];
            reg_acc += fmaf(q.x, q.x, fabsf(q.x));
            reg_acc += fmaf(q.y, q.y, fabsf(q.y));
            reg_acc += fmaf(q.z, q.z, fabsf(q.z));
            reg_acc += fmaf(q.w, q.w, fabsf(q.w));
            buf[dstb[w]     ] = q.x;
            buf[dstb[w] + 32] = q.y;
            buf[dstb[w] + 64] = q.z;
            buf[dstb[w] + 96] = q.w;
        }
        __syncthreads();

        if (s < 7) {
            size_t nb = base4 + (size_t)(s + 1) * 3200;
#pragma unroll
            for (int w = 0; w < 5; w++) v[w] = wp4[nb + tid + w * NTHR];
        }

        // Main vectorized gather: 8 tiles/thread, 4 j's per LDS.128.
        {
            const uint2 xw = *reinterpret_cast<const uint2*>(
                xch8 + b * L_ + (s << 5) + (tsub << 3));
            const int pbase = (s << 5) + (tsub << 3);
#pragma unroll
            for (int k = 0; k < 8; k++) {
                unsigned int word = (k < 4) ? xw.x : xw.y;
                int e = (word >> ((k & 3) * 8)) & 0xff;
                if (pbase + k > i) {
                    const float4 g = *reinterpret_cast<const float4*>(
                        &buf[tb + k * TILE_F + (e << 5) + (((jg ^ (e >> 2)) & 7) << 2)]);
                    a0 += g.x; a1 += g.y; a2 += g.z; a3 += g.w;
                }
            }
        }

        // Pair energy: warp 18, lane = b2, all 32 tiles.
        if (wid == 18) {
            const uint4 w0 = *reinterpret_cast<const uint4*>(xch8 + lane * L_ + (s << 5));
            const uint4 w1 = *reinterpret_cast<const uint4*>(xch8 + lane * L_ + (s << 5) + 16);
            unsigned int wv[8] = {w0.x, w0.y, w0.z, w0.w, w1.x, w1.y, w1.z, w1.w};
#pragma unroll
            for (int t = 0; t < 32; t++) {
                int e = (wv[t >> 2] >> ((t & 3) * 8)) & 0xff;
                pair_acc += buf[t * TILE_F + (e << 5) + (((xihi ^ (e >> 2)) & 7) << 2) + xilo];
            }
        }

        // Const terms: warp 19 lanes 0..19.  p<i: M[j][19];  p==i: M[j][j].
        if (jc >= 0 && jc < 20) {
            int tmax = i - (s << 5);           // t < tmax  <=>  p < i
            int lim = tmax < 32 ? tmax : 32;
            for (int t = 0; t < lim; t++) c_acc += buf[t * TILE_F + co19];
            if (tmax >= 0 && tmax < 32)
                c_acc += buf[tmax * TILE_F + (jc << 5) + (jc & 3)];
        }
        __syncthreads();
    }

    // ---- Epilogue (buf reused for partials) ----
    *reinterpret_cast<float4*>(&buf[tsub * 640 + b * A_ + (jg << 2)]) =
        make_float4(a0, a1, a2, a3);
    if (jc >= 0 && jc < 20) csts[jc] = c_acc;

    float rv = reg_acc;
#pragma unroll
    for (int o = 16; o > 0; o >>= 1) rv += __shfl_down_sync(0xffffffffu, rv, o);
    if (lane == 0) sredr[wid] = rv;

    if (wid == 18) {
        float pv = pair_acc;
#pragma unroll
        for (int o = 16; o > 0; o >>= 1) pv += __shfl_down_sync(0xffffffffu, pv, o);
        if (lane == 0) g_res[i][1] = (double)pv;
    }
    __syncthreads();

    {   // combine tsub partials + const + ws
        const int bb = tid / A_;
        const int j  = tid - bb * A_;
        float tot = buf[tid] + buf[640 + tid] + buf[1280 + tid] + buf[1920 + tid]
                  + csts[j] + wsrow[j];
        buf[tid] = tot;
        if (tid == 0) {
            double rs = 0.0;
            for (int w = 0; w < 20; w++) rs += (double)sredr[w];
            g_res[i][2] = rs;
        }
    }
    __syncthreads();

    if (tid < 32) {   // lse per b, minus single; warp-reduce to one double
        const float* row = &buf[tid * A_];
        float m = row[0];
#pragma unroll
        for (int j = 1; j < A_; j++) m = fmaxf(m, row[j]);
        float se = 0.f;
#pragma unroll
        for (int j = 0; j < A_; j++) se += __expf(row[j] - m);
        float lse = m + __logf(se);
        double val = (double)lse - (double)wsrow[xi[tid]];
#pragma unroll
        for (int o = 16; o > 0; o >>= 1) val += __shfl_down_sync(0xffffffffu, val, o);
        if (tid == 0) g_res[i][0] = val;
    }
}

// ---------------------------------------------------------------------------
// Kernel C: deterministic final reduction (1 CTA).
// ---------------------------------------------------------------------------
__global__ __launch_bounds__(256) void mrf_kernelC(const float* __restrict__ ws,
                                                   float* __restrict__ out) {
    const int tid = threadIdx.x;
    double LS = g_res[tid][0], PA = g_res[tid][1], RP = g_res[tid][2], RS = 0.0;
    for (int n = tid; n < L_ * A_; n += 256) {
        float w = ws[n];
        RS += (double)fabsf(w) + (double)w * (double)w;
    }
    __shared__ double s1[8], s2[8], s3[8], s4v[8];
#pragma unroll
    for (int o = 16; o > 0; o >>= 1) {
        LS += __shfl_down_sync(0xffffffffu, LS, o);
        PA += __shfl_down_sync(0xffffffffu, PA, o);
        RP += __shfl_down_sync(0xffffffffu, RP, o);
        RS += __shfl_down_sync(0xffffffffu, RS, o);
    }
    if ((tid & 31) == 0) {
        int w = tid >> 5;
        s1[w] = LS; s2[w] = PA; s3[w] = RP; s4v[w] = RS;
    }
    __syncthreads();
    if (tid == 0) {
        double ls = 0, pa = 0, rp = 0, rs = 0;
        for (int w = 0; w < 8; w++) { ls += s1[w]; pa += s2[w]; rp += s3[w]; rs += s4v[w]; }
        // LAMBDA_SINGLE = 1.0, LAMBDA_PAIR = 0.2*(L-1) = 51.0
        out[0] = (float)((ls - pa) / (double)B_ + 1.0 * rs + 51.0 * rp);
    }
}

extern "C" void kernel_launch(void* const* d_in, const int* in_sizes, int n_in,
                              void* d_out, int out_size) {
    (void)in_sizes; (void)n_in; (void)out_size;
    const int*   x  = (const int*)d_in[0];
    const float* ws = (const float*)d_in[1];
    const float* wp = (const float*)d_in[2];
    float* out = (float*)d_out;

    cudaFuncSetAttribute(mrf_kernelA, cudaFuncAttributeMaxDynamicSharedMemorySize, SMEM_BYTES);
    mrf_kernelA<<<L_, NTHR, SMEM_BYTES>>>(x, ws, wp);
    mrf_kernelC<<<1, 256>>>(ws, out);
}